// round 3
// baseline (speedup 1.0000x reference)
#include <cuda_runtime.h>
#include <cuda_bf16.h>
#include <math.h>

// Problem constants
#define T_  256
#define B_  128
#define H_  1024
#define L_  4
#define MTOT (T_ * B_)   // 32768

#define NBLK 128         // persistent blocks (<= SM count, co-resident)
#define NTHR 256
#define BK   64          // k-chunk for h staging

// Scratch: precomputed input projections for current layer + double-buffered h.
__device__ float g_P[(size_t)MTOT * H_];
__device__ float g_h[2][B_ * H_];

// grid barrier state
__device__ volatile unsigned g_bar_gen = 0;
__device__ unsigned g_bar_cnt = 0;

__device__ __forceinline__ void grid_barrier()
{
    __syncthreads();
    if (threadIdx.x == 0) {
        unsigned gen = g_bar_gen;            // read BEFORE arriving
        __threadfence();                     // make this block's writes visible
        if (atomicAdd(&g_bar_cnt, 1) == NBLK - 1) {
            atomicExch(&g_bar_cnt, 0);
            __threadfence();
            g_bar_gen = gen + 1;             // release
        } else {
            while (g_bar_gen == gen) { }     // spin in L2
            __threadfence();
        }
    }
    __syncthreads();
}

// ---------------------------------------------------------------------------
// Kernel 1: per-layer precompute  P = X @ Wi^T + (bi + bh)
// Classic 128x128x8 register-blocked SGEMM, 256 threads, 8x8 per thread.
// ---------------------------------------------------------------------------
#define PBM 128
#define PBN 128
#define PBK 8

__global__ __launch_bounds__(256) void gemm_pre(
    const float* __restrict__ X, const float* __restrict__ W,
    const float* __restrict__ bi, const float* __restrict__ bh)
{
    __shared__ float As[PBK][PBM];
    __shared__ float Bs[PBK][PBN];

    const int m0 = blockIdx.y * PBM;
    const int n0 = blockIdx.x * PBN;
    const int tid = threadIdx.x;
    const int tx = tid & 15;
    const int ty = tid >> 4;

    const int lr = tid >> 1;
    const int lc = (tid & 1) * 4;

    const float* Xp = X + (size_t)(m0 + lr) * H_ + lc;
    const float* Wp = W + (size_t)(n0 + lr) * H_ + lc;

    float acc[8][8];
    #pragma unroll
    for (int i = 0; i < 8; i++)
        #pragma unroll
        for (int j = 0; j < 8; j++) acc[i][j] = 0.0f;

    for (int k0 = 0; k0 < H_; k0 += PBK) {
        float4 xa = *(const float4*)(Xp + k0);
        float4 wb = *(const float4*)(Wp + k0);
        __syncthreads();
        As[lc + 0][lr] = xa.x; As[lc + 1][lr] = xa.y;
        As[lc + 2][lr] = xa.z; As[lc + 3][lr] = xa.w;
        Bs[lc + 0][lr] = wb.x; Bs[lc + 1][lr] = wb.y;
        Bs[lc + 2][lr] = wb.z; Bs[lc + 3][lr] = wb.w;
        __syncthreads();

        #pragma unroll
        for (int kk = 0; kk < PBK; kk++) {
            float a[8], b[8];
            *(float4*)(a)     = *(const float4*)&As[kk][ty * 8];
            *(float4*)(a + 4) = *(const float4*)&As[kk][ty * 8 + 4];
            *(float4*)(b)     = *(const float4*)&Bs[kk][tx * 8];
            *(float4*)(b + 4) = *(const float4*)&Bs[kk][tx * 8 + 4];
            #pragma unroll
            for (int i = 0; i < 8; i++)
                #pragma unroll
                for (int j = 0; j < 8; j++)
                    acc[i][j] = fmaf(a[i], b[j], acc[i][j]);
        }
    }

    float bias[8];
    #pragma unroll
    for (int j = 0; j < 8; j++) {
        int n = n0 + tx * 8 + j;
        bias[j] = bi[n] + bh[n];
    }
    #pragma unroll
    for (int i = 0; i < 8; i++) {
        int m = m0 + ty * 8 + i;
        float* Pr = g_P + (size_t)m * H_ + n0 + tx * 8;
        #pragma unroll
        for (int j = 0; j < 8; j++) Pr[j] = acc[i][j] + bias[j];
    }
}

// ---------------------------------------------------------------------------
// Kernel 2: persistent recurrence for one whole layer (all 256 steps).
// 128 blocks x 256 threads. Block owns 8 output columns; its Wh slice
// (8 x 1024 = 32 KB) lives in SMEM for the whole layer. Per step, h is
// streamed through a double-buffered [128 x BK] SMEM tile.
// Dyn smem layout: Whs[8*1024] | hs[2][128*65]
// ---------------------------------------------------------------------------
#define HS_STRIDE 65
#define SMEM_FLOATS (8 * H_ + 2 * B_ * HS_STRIDE)

__global__ __launch_bounds__(NTHR) void rnn_seq(
    const float* __restrict__ hx, const float* __restrict__ Wh,
    float* __restrict__ outx, float* __restrict__ hn)
{
    extern __shared__ float smem[];
    float* Whs = smem;                         // [8][1024]
    float* hs0 = smem + 8 * H_;                // [128][65]
    float* hs1 = hs0 + B_ * HS_STRIDE;

    const int tid = threadIdx.x;
    const int bid = blockIdx.x;
    const int n0  = bid * 8;
    const int c   = tid >> 7;          // 0/1: column group (4 cols each)
    const int b   = tid & 127;         // batch row

    // --- load Wh slice into SMEM (once per layer) ---
    {
        const float4* Wg = (const float4*)(Wh + (size_t)n0 * H_);
        float4* Ws4 = (float4*)Whs;
        #pragma unroll
        for (int i = 0; i < 8; i++)
            Ws4[tid + NTHR * i] = Wg[tid + NTHR * i];   // 2048 float4s
    }

    // --- init h: g_h[0] = hx (each of 32768 threads copies one float4) ---
    {
        int i = bid * NTHR + tid;
        ((float4*)g_h[0])[i] = ((const float4*)hx)[i];
    }
    grid_barrier();

    // loader indices for h tile: r = tid>>4 + 16*i, c4 = tid&15
    const int lr = tid >> 4;
    const int lc4 = tid & 15;

    const float* Wr0 = Whs + (4 * c + 0) * H_;
    const float* Wr1 = Whs + (4 * c + 1) * H_;
    const float* Wr2 = Whs + (4 * c + 2) * H_;
    const float* Wr3 = Whs + (4 * c + 3) * H_;

    for (int t = 0; t < T_; t++) {
        const float* __restrict__ hprev = g_h[t & 1];
        float* __restrict__ hnext = g_h[(t + 1) & 1];
        const float* __restrict__ Pt = g_P + (size_t)t * B_ * H_;
        float* __restrict__ ox = outx + (size_t)t * B_ * H_;

        float acc0 = 0.f, acc1 = 0.f, acc2 = 0.f, acc3 = 0.f;

        // prefetch chunk 0
        float4 pf[8];
        #pragma unroll
        for (int i = 0; i < 8; i++)
            pf[i] = *(const float4*)&hprev[(size_t)(lr + 16 * i) * H_ + lc4 * 4];

        #pragma unroll 1
        for (int kc = 0; kc < H_ / BK; kc++) {
            float* buf = (kc & 1) ? hs1 : hs0;
            // stage prefetched chunk into SMEM
            #pragma unroll
            for (int i = 0; i < 8; i++) {
                int r = lr + 16 * i;
                float* d = &buf[r * HS_STRIDE + lc4 * 4];
                d[0] = pf[i].x; d[1] = pf[i].y; d[2] = pf[i].z; d[3] = pf[i].w;
            }
            __syncthreads();
            // prefetch next chunk
            if (kc + 1 < H_ / BK) {
                int kb = (kc + 1) * BK;
                #pragma unroll
                for (int i = 0; i < 8; i++)
                    pf[i] = *(const float4*)&hprev[(size_t)(lr + 16 * i) * H_ + kb + lc4 * 4];
            }
            // compute on this chunk
            const float* hrow = &buf[b * HS_STRIDE];
            const int kb = kc * BK;
            #pragma unroll
            for (int kk4 = 0; kk4 < BK / 4; kk4++) {
                const int k = kk4 * 4;
                float h0 = hrow[k], h1 = hrow[k + 1], h2 = hrow[k + 2], h3 = hrow[k + 3];
                float4 w0 = *(const float4*)&Wr0[kb + k];
                float4 w1 = *(const float4*)&Wr1[kb + k];
                float4 w2 = *(const float4*)&Wr2[kb + k];
                float4 w3 = *(const float4*)&Wr3[kb + k];
                acc0 = fmaf(h0, w0.x, acc0); acc0 = fmaf(h1, w0.y, acc0);
                acc0 = fmaf(h2, w0.z, acc0); acc0 = fmaf(h3, w0.w, acc0);
                acc1 = fmaf(h0, w1.x, acc1); acc1 = fmaf(h1, w1.y, acc1);
                acc1 = fmaf(h2, w1.z, acc1); acc1 = fmaf(h3, w1.w, acc1);
                acc2 = fmaf(h0, w2.x, acc2); acc2 = fmaf(h1, w2.y, acc2);
                acc2 = fmaf(h2, w2.z, acc2); acc2 = fmaf(h3, w2.w, acc2);
                acc3 = fmaf(h0, w3.x, acc3); acc3 = fmaf(h1, w3.y, acc3);
                acc3 = fmaf(h2, w3.z, acc3); acc3 = fmaf(h3, w3.w, acc3);
            }
        }

        // epilogue: add P, tanh, store to h double-buffer + output x
        {
            const size_t base = (size_t)b * H_ + n0 + 4 * c;
            float v0 = tanhf(acc0 + Pt[base + 0]);
            float v1 = tanhf(acc1 + Pt[base + 1]);
            float v2 = tanhf(acc2 + Pt[base + 2]);
            float v3 = tanhf(acc3 + Pt[base + 3]);
            hnext[base + 0] = v0; hnext[base + 1] = v1;
            hnext[base + 2] = v2; hnext[base + 3] = v3;
            ox[base + 0] = v0; ox[base + 1] = v1;
            ox[base + 2] = v2; ox[base + 3] = v3;
            if (t == T_ - 1) {
                hn[base + 0] = v0; hn[base + 1] = v1;
                hn[base + 2] = v2; hn[base + 3] = v3;
            }
        }
        grid_barrier();
    }
}

// ---------------------------------------------------------------------------
// Launch: per layer: 1 precompute GEMM + 1 persistent recurrence kernel.
// Total 8 graph nodes.
// ---------------------------------------------------------------------------
extern "C" void kernel_launch(void* const* d_in, const int* in_sizes, int n_in,
                              void* d_out, int out_size)
{
    const float* inputs = (const float*)d_in[0];   // [T,B,H]
    const float* hxs    = (const float*)d_in[1];   // [L,B,H]
    const float* W_ih   = (const float*)d_in[2];   // [L,H,H]
    const float* b_ih   = (const float*)d_in[3];   // [L,H]
    const float* W_hh   = (const float*)d_in[4];   // [L,H,H]
    const float* b_hh   = (const float*)d_in[5];   // [L,H]

    float* out  = (float*)d_out;
    float* outx = out;                               // [T,B,H]
    float* outh = out + (size_t)T_ * B_ * H_;        // [L,B,H]

    static bool attr_done = false;
    if (!attr_done) {
        cudaFuncSetAttribute(rnn_seq, cudaFuncAttributeMaxDynamicSharedMemorySize,
                             SMEM_FLOATS * (int)sizeof(float));
        attr_done = true;
    }

    dim3 pre_grid(H_ / PBN, MTOT / PBM);             // (8, 256)

    for (int l = 0; l < L_; l++) {
        const float* x_l = (l == 0) ? inputs : outx;
        gemm_pre<<<pre_grid, 256>>>(x_l,
                                    W_ih + (size_t)l * H_ * H_,
                                    b_ih + (size_t)l * H_,
                                    b_hh + (size_t)l * H_);
        rnn_seq<<<NBLK, NTHR, SMEM_FLOATS * sizeof(float)>>>(
            hxs + (size_t)l * B_ * H_,
            W_hh + (size_t)l * H_ * H_,
            outx,
            outh + (size_t)l * B_ * H_);
    }
}